// round 3
// baseline (speedup 1.0000x reference)
#include <cuda_runtime.h>
#include <math.h>

#define TPB 256

// shared layout (floats)
#define LDH   128            // h row stride
#define LDS1  388            // s1 row stride (qkv / scratch), 388%32=4, mult of 4 for float4
#define LDKT  69             // kT row stride (k-transposed), 69%32=5 -> conflict-free
#define LDSTG 132            // weight stage row stride (128+4), float4 conflict-free

#define OFF_H   0
#define OFF_S1  8704                     // h: 68*128
#define OFF_KT  (OFF_S1 + 68*LDS1)      // s1: 68*388 = 26384
#define OFF_STG (OFF_KT + 128*LDKT)     // kT: 128*69 = 8832
#define SMEM_FLOATS (OFF_STG + 8448)    // stage: 64*132 = 8448
// total = 8704+26384+8832+8448 = 52368 floats = 209472 bytes

__device__ __forceinline__ float4 ld4(const float* p) {
    return *reinterpret_cast<const float4*>(p);
}
__device__ __forceinline__ float warp_sum(float v) {
#pragma unroll
    for (int o = 16; o > 0; o >>= 1) v += __shfl_xor_sync(0xffffffffu, v, o);
    return v;
}
__device__ __forceinline__ float warp_max(float v) {
#pragma unroll
    for (int o = 16; o > 0; o >>= 1) v = fmaxf(v, __shfl_xor_sync(0xffffffffu, v, o));
    return v;
}

// GEMM: out[t][j] = A[t][:] . Wg[j][:] + bias[j], t in [0,65), j in [0,J)
// A in smem (rows padded to 68), Wg global row-major [J][K], K in {128,256}, J mult of 64.
// Stage: 64 W-rows x 128 k-chunk in smem. Warp w owns t-tiles tt = w, w+8, w+16.
// TRANSPOSED=1 stores Out[j*LDKT + t] (for k^T); RELU applies max(0,.).
template<int TRANSPOSED, int RELU>
__device__ void gemm_sm(const float* __restrict__ A, int lda,
                        const float* __restrict__ Wg, int K, int J,
                        const float* __restrict__ bias,
                        float* __restrict__ Out, int ldo,
                        float* __restrict__ stg,
                        int tid, int lane, int wid)
{
    const int nkb = K >> 7;
    const int njb = J >> 6;
    for (int jb = 0; jb < njb; ++jb) {
        float acc[3][4][2];
#pragma unroll
        for (int s = 0; s < 3; ++s)
#pragma unroll
            for (int i = 0; i < 4; ++i) { acc[s][i][0] = 0.f; acc[s][i][1] = 0.f; }

        for (int kb = 0; kb < nkb; ++kb) {
            __syncthreads();                       // protect stage from previous users
            const float* wsrc = Wg + (jb * 64) * K + kb * 128;
#pragma unroll
            for (int i = tid; i < 2048; i += TPB) {        // 64 rows x 32 float4
                int j  = i >> 5;
                int k4 = (i & 31) << 2;
                *reinterpret_cast<float4*>(stg + j * LDSTG + k4) = ld4(wsrc + j * K + k4);
            }
            __syncthreads();
#pragma unroll
            for (int s = 0; s < 3; ++s) {
                int tt = wid + s * 8;
                if (tt < 17) {
                    const float* Ab  = A + tt * 4 * lda + kb * 128;
                    const float* wp0 = stg + lane * LDSTG;
                    const float* wp1 = wp0 + 32 * LDSTG;
#pragma unroll 4
                    for (int k4 = 0; k4 < 128; k4 += 4) {
                        float4 w0 = ld4(wp0 + k4);
                        float4 w1 = ld4(wp1 + k4);
#pragma unroll
                        for (int i = 0; i < 4; ++i) {
                            float4 a = ld4(Ab + i * lda + k4);
                            acc[s][i][0] = fmaf(a.x, w0.x, acc[s][i][0]);
                            acc[s][i][0] = fmaf(a.y, w0.y, acc[s][i][0]);
                            acc[s][i][0] = fmaf(a.z, w0.z, acc[s][i][0]);
                            acc[s][i][0] = fmaf(a.w, w0.w, acc[s][i][0]);
                            acc[s][i][1] = fmaf(a.x, w1.x, acc[s][i][1]);
                            acc[s][i][1] = fmaf(a.y, w1.y, acc[s][i][1]);
                            acc[s][i][1] = fmaf(a.z, w1.z, acc[s][i][1]);
                            acc[s][i][1] = fmaf(a.w, w1.w, acc[s][i][1]);
                        }
                    }
                }
            }
        }
        // store
#pragma unroll
        for (int s = 0; s < 3; ++s) {
            int tt = wid + s * 8;
            if (tt >= 17) continue;
#pragma unroll
            for (int r = 0; r < 2; ++r) {
                int j = jb * 64 + lane + 32 * r;
                float bv = bias[j];
#pragma unroll
                for (int i = 0; i < 4; ++i) {
                    int t = tt * 4 + i;
                    if (t < 65) {
                        float v = acc[s][i][r] + bv;
                        if (RELU) v = fmaxf(v, 0.f);
                        if (TRANSPOSED) Out[j * LDKT + t] = v;
                        else            Out[t * ldo + j]  = v;
                    }
                }
            }
        }
    }
}

// h[t] = LN(h[t] + g[t]) * sc + bt  for t < 65; g has row stride LDS1
__device__ __forceinline__ void layer_norm_res(float* __restrict__ h,
                                               const float* __restrict__ g,
                                               const float* __restrict__ sc,
                                               const float* __restrict__ bt,
                                               int lane, int wid)
{
    for (int t = wid; t < 65; t += 8) {
        float v[4];
        float s = 0.f;
#pragma unroll
        for (int i = 0; i < 4; ++i) {
            int c = lane + 32 * i;
            v[i] = h[t * LDH + c] + g[t * LDS1 + c];
            s += v[i];
        }
        s = warp_sum(s);
        float mean = s * 0.0078125f;
        float var = 0.f;
#pragma unroll
        for (int i = 0; i < 4; ++i) { float d = v[i] - mean; var = fmaf(d, d, var); }
        var = warp_sum(var) * 0.0078125f;
        float r = rsqrtf(var + 1e-5f);
#pragma unroll
        for (int i = 0; i < 4; ++i) {
            int c = lane + 32 * i;
            h[t * LDH + c] = (v[i] - mean) * r * sc[c] + bt[c];
        }
    }
}

__global__ void __launch_bounds__(TPB, 1)
vit_kernel(const float* __restrict__ x,
           const float* __restrict__ patch_w,
           const float* __restrict__ patch_b,
           const float* __restrict__ cls_token,
           const float* __restrict__ pos_embed,
           const float* __restrict__ qkv_w,
           const float* __restrict__ qkv_b,
           const float* __restrict__ out_w,
           const float* __restrict__ out_b,
           const float* __restrict__ ln1_s,
           const float* __restrict__ ln1_b,
           const float* __restrict__ ln2_s,
           const float* __restrict__ ln2_b,
           const float* __restrict__ ff1_w,
           const float* __restrict__ ff1_b,
           const float* __restrict__ ff2_w,
           const float* __restrict__ ff2_b,
           const float* __restrict__ qr1_w,
           const float* __restrict__ qr1_b,
           const float* __restrict__ qr2_w,
           const float* __restrict__ qr2_b,
           const float* __restrict__ q_weights,
           const float* __restrict__ clf_w,
           const float* __restrict__ clf_b,
           float* __restrict__ y)
{
    extern __shared__ float sm[];
    float* h   = sm + OFF_H;    // [68][128]
    float* s1  = sm + OFF_S1;   // [68][388]: q 0..127 | k-out/attn-scratch 128..255 | v 256..383
    float* kT  = sm + OFF_KT;   // [128][69]
    float* stg = sm + OFF_STG;  // 8448 floats: W stage / x image / softmax probs

    const int tid  = threadIdx.x;
    const int lane = tid & 31;
    const int wid  = tid >> 5;
    const int b    = blockIdx.x;

    // ---------------- patch embed ----------------
    const float* xb = x + (size_t)b * 3072;
    for (int i = tid; i < 3072; i += TPB) stg[i] = xb[i];
    for (int i = tid; i < 6144; i += TPB) {          // patch_w [d][ck] -> s1[ck][d]
        int d = i / 48, ck = i - d * 48;
        s1[ck * 128 + d] = patch_w[i];
    }
    __syncthreads();
    for (int idx = tid; idx < 8192; idx += TPB) {
        int tkn = idx >> 7, d = idx & 127;
        int pi = tkn >> 3, pj = tkn & 7;
        const float* xp = stg + pi * 128 + pj * 4;
        float acc = patch_b[d];
#pragma unroll
        for (int c = 0; c < 3; ++c)
#pragma unroll
            for (int p = 0; p < 4; ++p)
#pragma unroll
                for (int q = 0; q < 4; ++q)
                    acc = fmaf(xp[c * 1024 + p * 32 + q], s1[(c * 16 + p * 4 + q) * 128 + d], acc);
        h[(1 + tkn) * LDH + d] = acc + pos_embed[(1 + tkn) * 128 + d];
    }
    for (int d = tid; d < 128; d += TPB) h[d] = cls_token[d] + pos_embed[d];
    // gemm's leading __syncthreads orders these writes before stage reuse.

    const float SCALE = 0.17677669529663687f;   // 1/sqrt(32)

    for (int li = 0; li < 4; ++li) {
        const float* qw = qkv_w + li * 49152;
        const float* qb = qkv_b + li * 384;
        // Q -> s1[:,0:128]
        gemm_sm<0, 0>(h, LDH, qw,          128, 128, qb,        s1,        LDS1, stg, tid, lane, wid);
        // K -> kT (transposed)
        gemm_sm<1, 0>(h, LDH, qw + 16384,  128, 128, qb + 128,  kT,        0,    stg, tid, lane, wid);
        // V -> s1[:,256:384]
        gemm_sm<0, 0>(h, LDH, qw + 32768,  128, 128, qb + 256,  s1 + 256,  LDS1, stg, tid, lane, wid);
        __syncthreads();   // kT / v visible to all warps

        // ---------------- attention (row partition == warp id, no block syncs) ----------------
        for (int hd = 0; hd < 4; ++hd) {
            const int ho = hd * 32;
            for (int tt = wid; tt < 17; tt += 8) {
                const int t0 = tt * 4;
                float a0[4], a1[4], a64[4];
#pragma unroll
                for (int i = 0; i < 4; ++i) { a0[i] = 0.f; a1[i] = 0.f; a64[i] = 0.f; }
                const float* qrow = s1 + t0 * LDS1 + ho;
                const float* kb   = kT + ho * LDKT;
#pragma unroll 8
                for (int k = 0; k < 32; ++k) {
                    float k0  = kb[k * LDKT + lane];
                    float k1  = kb[k * LDKT + 32 + lane];
                    float k64 = kb[k * LDKT + 64];
#pragma unroll
                    for (int i = 0; i < 4; ++i) {
                        float qv = qrow[i * LDS1 + k];
                        a0[i]  = fmaf(qv, k0,  a0[i]);
                        a1[i]  = fmaf(qv, k1,  a1[i]);
                        a64[i] = fmaf(qv, k64, a64[i]);
                    }
                }
                // softmax rows t0..t0+3 (guarded), probs -> stg[t][u], stride 68
#pragma unroll
                for (int i = 0; i < 4; ++i) {
                    int t = t0 + i;
                    if (t >= 65) break;
                    float v0 = a0[i] * SCALE, v1 = a1[i] * SCALE, v2 = a64[i] * SCALE;
                    float m = warp_max(fmaxf(fmaxf(v0, v1), v2));
                    float e0 = expf(v0 - m), e1 = expf(v1 - m), e2 = expf(v2 - m);
                    float ssum = warp_sum(e0 + e1 + (lane == 0 ? e2 : 0.f));
                    float inv = 1.f / ssum;
                    stg[t * 68 + lane]      = e0 * inv;
                    stg[t * 68 + 32 + lane] = e1 * inv;
                    if (lane == 0) stg[t * 68 + 64] = e2 * inv;
                }
                __syncwarp();
                // O = S @ V_h, write into q-slot of this head (already consumed)
                float oc[4] = {0.f, 0.f, 0.f, 0.f};
                const float* vb = s1 + 256 + ho + lane;
                for (int u = 0; u < 65; ++u) {
                    float vv = vb[u * LDS1];
#pragma unroll
                    for (int i = 0; i < 4; ++i)
                        oc[i] = fmaf(stg[(t0 + i) * 68 + u], vv, oc[i]);
                }
#pragma unroll
                for (int i = 0; i < 4; ++i)
                    if (t0 + i < 65) s1[(t0 + i) * LDS1 + ho + lane] = oc[i];
                __syncwarp();
            }
        }

        // out-proj: s1[:,0:128] @ W^T -> s1[:,128:256]
        gemm_sm<0, 0>(s1, LDS1, out_w + li * 16384, 128, 128, out_b + li * 128,
                      s1 + 128, LDS1, stg, tid, lane, wid);
        __syncthreads();
        layer_norm_res(h, s1 + 128, ln1_s + li * 128, ln1_b + li * 128, lane, wid);
        __syncthreads();

        // FF1 (relu) -> s1[:,0:256]
        gemm_sm<0, 1>(h, LDH, ff1_w + li * 32768, 128, 256, ff1_b + li * 256,
                      s1, LDS1, stg, tid, lane, wid);
        // FF2 -> s1[:,256:384]   (reads s1[:,0:256], K=256)
        gemm_sm<0, 0>(s1, LDS1, ff2_w + li * 32768, 256, 128, ff2_b + li * 128,
                      s1 + 256, LDS1, stg, tid, lane, wid);
        __syncthreads();
        layer_norm_res(h, s1 + 256, ln2_s + li * 128, ln2_b + li * 128, lane, wid);
        __syncthreads();
    }

    // ---------------- readout head (warp 0) ----------------
    if (wid == 0) {
        // a = relu(cls @ qr1_w^T + qr1_b), lane j = feature j
        float accq = qr1_b[lane];
        const float* wr = qr1_w + lane * 128;
#pragma unroll 8
        for (int k = 0; k < 128; k += 4) {
            float4 hv = ld4(h + k);
            float4 wv = ld4(wr + k);
            accq = fmaf(hv.x, wv.x, accq);
            accq = fmaf(hv.y, wv.y, accq);
            accq = fmaf(hv.z, wv.z, accq);
            accq = fmaf(hv.w, wv.w, accq);
        }
        stg[lane] = fmaxf(accq, 0.f);
        __syncwarp();
        float qo[4];
#pragma unroll
        for (int m = 0; m < 4; ++m) {
            float s = qr2_b[m];
            for (int k = 0; k < 32; ++k) s = fmaf(stg[k], qr2_w[m * 32 + k], s);
            float qin = tanhf(s);
            qo[m] = cosf(qin) * cosf(q_weights[m]);
        }
        qo[1] *= qo[0]; qo[2] *= qo[1]; qo[3] *= qo[2];   // cumprod
        if (lane < 10) {
            float o = clf_b[lane];
            const float* cw = clf_w + lane * 132;
            for (int k = 0; k < 128; ++k) o = fmaf(h[k], cw[k], o);
#pragma unroll
            for (int m = 0; m < 4; ++m) o = fmaf(qo[m], cw[128 + m], o);
            y[b * 10 + lane] = o;
        }
    }
}

extern "C" void kernel_launch(void* const* d_in, const int* in_sizes, int n_in,
                              void* d_out, int out_size)
{
    const int B = in_sizes[0] / 3072;   // x = (B,3,32,32)
    cudaFuncSetAttribute(vit_kernel, cudaFuncAttributeMaxDynamicSharedMemorySize,
                         SMEM_FLOATS * (int)sizeof(float));
    vit_kernel<<<B, TPB, SMEM_FLOATS * sizeof(float)>>>(
        (const float*)d_in[0],  (const float*)d_in[1],  (const float*)d_in[2],
        (const float*)d_in[3],  (const float*)d_in[4],  (const float*)d_in[5],
        (const float*)d_in[6],  (const float*)d_in[7],  (const float*)d_in[8],
        (const float*)d_in[9],  (const float*)d_in[10], (const float*)d_in[11],
        (const float*)d_in[12], (const float*)d_in[13], (const float*)d_in[14],
        (const float*)d_in[15], (const float*)d_in[16], (const float*)d_in[17],
        (const float*)d_in[18], (const float*)d_in[19], (const float*)d_in[20],
        (const float*)d_in[21], (const float*)d_in[22], (const float*)d_in[23],
        (float*)d_out);
}